// round 4
// baseline (speedup 1.0000x reference)
#include <cuda_runtime.h>
#include <cuda_pipeline.h>
#include <math.h>

#define D_INNER 8192
#define D_MODEL 4096
#define DT_RANK 8
#define D_STATE 16
#define XP_DIM  (DT_RANK + 2 * D_STATE)   // 40

#define GRID_P   296        // 2 persistent blocks per SM (148 SMs)
#define CHUNK_C  512        // chunk columns (floats)
#define CHUNK_F4 1024       // 8 rows * 128 float4 per chunk
#define KT_XP    1024

// Scratch
__device__ float g_x_conv[D_INNER];
__device__ float g_z_silu[D_INNER];
__device__ float g_xp[XP_DIM];
__device__ float g_y[D_INNER];

// ---------------------------------------------------------------------------
// Kernel 1 (persistent): xz = W_in @ x (16384 x 4096) + fused conv/silu.
// Tiles: 2048 (8 rows x full 4096 K, 8 chunks of 512). 3-stage cp.async pipe.
// smem: x (16KB) + 3 chunk buffers (48KB) = 64KB dynamic.
// ---------------------------------------------------------------------------
__global__ __launch_bounds__(256) void k_win_p(
    const float* __restrict__ W_in,
    const float* __restrict__ x,
    const float* __restrict__ conv_buffer,
    const float* __restrict__ conv_w,
    const float* __restrict__ conv_b)
{
    extern __shared__ float sm[];
    float4* vec4 = (float4*)sm;                    // 1024 f4 (x)
    float4* bufs = (float4*)(sm + D_MODEL);        // 3 * 1024 f4

    const int tid = threadIdx.x;
    const int b   = blockIdx.x;
    if (b == 0 && tid < XP_DIM) g_xp[tid] = 0.0f;

    // stage x into shared (visibility covered by first loop barrier)
    const float4* x4 = (const float4*)x;
    #pragma unroll
    for (int i = tid; i < D_MODEL / 4; i += 256) vec4[i] = x4[i];

    const int ntiles = (2048 - b + GRID_P - 1) / GRID_P;   // tiles b, b+296, ...
    const int T = ntiles * 8;                               // chunks for this block

    auto issue = [&](int s, int bi) {
        const int t = b + (s >> 3) * GRID_P;   // tile id
        const int c = s & 7;                   // chunk within tile
        float4* dst = bufs + bi * CHUNK_F4;
        const float* wb = W_in + (size_t)(t * 8) * D_MODEL + c * CHUNK_C;
        #pragma unroll
        for (int k = 0; k < 4; ++k) {
            const int f   = k * 256 + tid;     // 0..1023
            const int row = f >> 7;            // /128
            const int col = f & 127;
            __pipeline_memcpy_async(dst + f,
                (const float4*)(wb + (size_t)row * D_MODEL) + col, 16);
        }
    };

    if (T > 0) issue(0, 0);
    __pipeline_commit();
    if (T > 1) issue(1, 1);
    __pipeline_commit();

    const int warp = tid >> 5, lane = tid & 31;
    float acc0 = 0.0f, acc1 = 0.0f;

    for (int s = 0; s < T; ++s) {
        __pipeline_wait_prior(1);
        __syncthreads();
        const int c = s & 7;
        const float4* wb = bufs + (s % 3) * CHUNK_F4 + warp * 128;
        const float4* vb = vec4 + c * 128;
        float4 w0 = wb[lane],      v0 = vb[lane];
        float4 w1 = wb[lane + 32], v1 = vb[lane + 32];
        float4 w2 = wb[lane + 64], v2 = vb[lane + 64];
        float4 w3 = wb[lane + 96], v3 = vb[lane + 96];
        acc0 = fmaf(w0.x, v0.x, acc0); acc0 = fmaf(w0.y, v0.y, acc0);
        acc0 = fmaf(w0.z, v0.z, acc0); acc0 = fmaf(w0.w, v0.w, acc0);
        acc1 = fmaf(w1.x, v1.x, acc1); acc1 = fmaf(w1.y, v1.y, acc1);
        acc1 = fmaf(w1.z, v1.z, acc1); acc1 = fmaf(w1.w, v1.w, acc1);
        acc0 = fmaf(w2.x, v2.x, acc0); acc0 = fmaf(w2.y, v2.y, acc0);
        acc0 = fmaf(w2.z, v2.z, acc0); acc0 = fmaf(w2.w, v2.w, acc0);
        acc1 = fmaf(w3.x, v3.x, acc1); acc1 = fmaf(w3.y, v3.y, acc1);
        acc1 = fmaf(w3.z, v3.z, acc1); acc1 = fmaf(w3.w, v3.w, acc1);

        if (c == 7) {
            float a = acc0 + acc1;
            #pragma unroll
            for (int o = 16; o; o >>= 1) a += __shfl_xor_sync(0xffffffffu, a, o);
            if (lane == 0) {
                const int t   = b + (s >> 3) * GRID_P;
                const int row = t * 8 + warp;
                if (row < D_INNER) {
                    float b1 = conv_buffer[row * 3 + 1];
                    float b2 = conv_buffer[row * 3 + 2];
                    float4 cw = ((const float4*)conv_w)[row];
                    float ss = fmaf(b1, cw.x, fmaf(b2, cw.y,
                               fmaf(a, cw.z, fmaf(a, cw.w, conv_b[row]))));
                    g_x_conv[row] = ss / (1.0f + expf(-ss));
                } else {
                    g_z_silu[row - D_INNER] = a / (1.0f + expf(-a));
                }
            }
            acc0 = 0.0f; acc1 = 0.0f;
        }
        if (s + 2 < T) issue(s + 2, (s + 2) % 3);
        __pipeline_commit();                     // empty group near end keeps counts uniform
    }
}

// ---------------------------------------------------------------------------
// Kernel 2: xp = W_xp @ x_conv  (40 x 8192). Split-K grid (40, 8),
// atomicAdd into g_xp. Also zeroes d_out[0:4096] for k_wout's atomics.
// ---------------------------------------------------------------------------
__global__ __launch_bounds__(256) void k_xp(const float* __restrict__ W_xp,
                                            float* __restrict__ d_out)
{
    __shared__ float red[8];
    const int row   = blockIdx.x;
    const int kbase = blockIdx.y * KT_XP;
    const int tid   = threadIdx.x;

    const int bflat = blockIdx.y * XP_DIM + blockIdx.x;
    if (bflat < D_MODEL / 256) d_out[bflat * 256 + tid] = 0.0f;

    const float4* w4 = (const float4*)(W_xp + (size_t)row * D_INNER + kbase);
    const float4* v4 = (const float4*)(g_x_conv + kbase);

    float acc = 0.0f;
    #pragma unroll
    for (int i = tid; i < KT_XP / 4; i += 256) {
        float4 w = __ldcs(&w4[i]);
        float4 v = v4[i];
        acc = fmaf(w.x, v.x, acc);
        acc = fmaf(w.y, v.y, acc);
        acc = fmaf(w.z, v.z, acc);
        acc = fmaf(w.w, v.w, acc);
    }
    #pragma unroll
    for (int o = 16; o; o >>= 1) acc += __shfl_xor_sync(0xffffffffu, acc, o);
    const int warp = tid >> 5, lane = tid & 31;
    if (lane == 0) red[warp] = acc;
    __syncthreads();
    if (warp == 0) {
        float a = (lane < 8) ? red[lane] : 0.0f;
        #pragma unroll
        for (int o = 4; o; o >>= 1) a += __shfl_xor_sync(0xffffffffu, a, o);
        if (lane == 0) atomicAdd(&g_xp[row], a);
    }
}

// ---------------------------------------------------------------------------
// Kernel 3: per-channel SSM update. Writes new_h into d_out[4096:], y -> g_y.
// ---------------------------------------------------------------------------
__global__ __launch_bounds__(256) void k_ssm(
    const float* __restrict__ W_dt,
    const float* __restrict__ b_dt,
    const float* __restrict__ ssm_state,
    const float* __restrict__ A_log,
    const float* __restrict__ D_param,
    float* __restrict__ d_out)
{
    __shared__ float sxp[XP_DIM];
    const int tid = threadIdx.x;
    if (tid < XP_DIM) sxp[tid] = g_xp[tid];
    __syncthreads();

    const int ch = blockIdx.x * 256 + tid;

    float dtr = b_dt[ch];
    const float4* wd4 = (const float4*)(W_dt + (size_t)ch * DT_RANK);
    float4 w0 = wd4[0], w1 = wd4[1];
    dtr = fmaf(w0.x, sxp[0], dtr);
    dtr = fmaf(w0.y, sxp[1], dtr);
    dtr = fmaf(w0.z, sxp[2], dtr);
    dtr = fmaf(w0.w, sxp[3], dtr);
    dtr = fmaf(w1.x, sxp[4], dtr);
    dtr = fmaf(w1.y, sxp[5], dtr);
    dtr = fmaf(w1.z, sxp[6], dtr);
    dtr = fmaf(w1.w, sxp[7], dtr);
    float dt = (dtr > 20.0f) ? dtr : log1pf(expf(dtr));

    const float xc = g_x_conv[ch];
    const float* al = A_log + (size_t)ch * D_STATE;
    const float* st = ssm_state + (size_t)ch * D_STATE;
    float* hout = d_out + D_MODEL + (size_t)ch * D_STATE;

    float acc = 0.0f;
    #pragma unroll
    for (int s = 0; s < D_STATE; s++) {
        float A    = -expf(al[s]);
        float abar = expf(dt * A);
        float h    = fmaf(abar, st[s], dt * sxp[DT_RANK + s] * xc);
        hout[s] = h;
        acc = fmaf(h, sxp[DT_RANK + D_STATE + s], acc);
    }
    g_y[ch] = fmaf(D_param[ch], xc, acc) * g_z_silu[ch];
}

// ---------------------------------------------------------------------------
// Kernel 4 (persistent): out = W_out @ y (4096 x 8192).
// Tiles: 2048 (8 rows x 2048 cols = K/4; 4 chunks of 512). 3-stage cp.async.
// Epilogue: atomicAdd per row per K-quarter (out zeroed by k_xp).
// smem: y (32KB) + 3 chunk buffers (48KB) = 80KB dynamic.
// ---------------------------------------------------------------------------
__global__ __launch_bounds__(256) void k_wout_p(
    const float* __restrict__ W_out,
    float* __restrict__ out)
{
    extern __shared__ float sm[];
    float4* vec4 = (float4*)sm;                    // 2048 f4 (y)
    float4* bufs = (float4*)(sm + D_INNER);        // 3 * 1024 f4

    const int tid = threadIdx.x;
    const int b   = blockIdx.x;

    const float4* y4 = (const float4*)g_y;
    #pragma unroll
    for (int i = tid; i < D_INNER / 4; i += 256) vec4[i] = y4[i];

    const int ntiles = (2048 - b + GRID_P - 1) / GRID_P;
    const int T = ntiles * 4;

    auto issue = [&](int s, int bi) {
        const int t  = b + (s >> 2) * GRID_P;
        const int c  = s & 3;
        const int kb = (t & 3) * 2048 + c * CHUNK_C;
        const int r0 = (t >> 2) * 8;
        float4* dst = bufs + bi * CHUNK_F4;
        const float* wb = W_out + (size_t)r0 * D_INNER + kb;
        #pragma unroll
        for (int k = 0; k < 4; ++k) {
            const int f   = k * 256 + tid;
            const int row = f >> 7;
            const int col = f & 127;
            __pipeline_memcpy_async(dst + f,
                (const float4*)(wb + (size_t)row * D_INNER) + col, 16);
        }
    };

    if (T > 0) issue(0, 0);
    __pipeline_commit();
    if (T > 1) issue(1, 1);
    __pipeline_commit();

    const int warp = tid >> 5, lane = tid & 31;
    float acc0 = 0.0f, acc1 = 0.0f;

    for (int s = 0; s < T; ++s) {
        __pipeline_wait_prior(1);
        __syncthreads();
        const int t  = b + (s >> 2) * GRID_P;
        const int c  = s & 3;
        const int kb4 = ((t & 3) * 2048 + c * CHUNK_C) >> 2;
        const float4* wb = bufs + (s % 3) * CHUNK_F4 + warp * 128;
        const float4* vb = vec4 + kb4;
        float4 w0 = wb[lane],      v0 = vb[lane];
        float4 w1 = wb[lane + 32], v1 = vb[lane + 32];
        float4 w2 = wb[lane + 64], v2 = vb[lane + 64];
        float4 w3 = wb[lane + 96], v3 = vb[lane + 96];
        acc0 = fmaf(w0.x, v0.x, acc0); acc0 = fmaf(w0.y, v0.y, acc0);
        acc0 = fmaf(w0.z, v0.z, acc0); acc0 = fmaf(w0.w, v0.w, acc0);
        acc1 = fmaf(w1.x, v1.x, acc1); acc1 = fmaf(w1.y, v1.y, acc1);
        acc1 = fmaf(w1.z, v1.z, acc1); acc1 = fmaf(w1.w, v1.w, acc1);
        acc0 = fmaf(w2.x, v2.x, acc0); acc0 = fmaf(w2.y, v2.y, acc0);
        acc0 = fmaf(w2.z, v2.z, acc0); acc0 = fmaf(w2.w, v2.w, acc0);
        acc1 = fmaf(w3.x, v3.x, acc1); acc1 = fmaf(w3.y, v3.y, acc1);
        acc1 = fmaf(w3.z, v3.z, acc1); acc1 = fmaf(w3.w, v3.w, acc1);

        if (c == 3) {
            float a = acc0 + acc1;
            #pragma unroll
            for (int o = 16; o; o >>= 1) a += __shfl_xor_sync(0xffffffffu, a, o);
            if (lane == 0) atomicAdd(&out[(t >> 2) * 8 + warp], a);
            acc0 = 0.0f; acc1 = 0.0f;
        }
        if (s + 2 < T) issue(s + 2, (s + 2) % 3);
        __pipeline_commit();
    }
}

// ---------------------------------------------------------------------------
extern "C" void kernel_launch(void* const* d_in, const int* in_sizes, int n_in,
                              void* d_out, int out_size)
{
    const float* x           = (const float*)d_in[0];
    const float* ssm_state   = (const float*)d_in[1];
    const float* conv_buffer = (const float*)d_in[2];
    const float* W_in        = (const float*)d_in[3];
    const float* conv_w      = (const float*)d_in[4];
    const float* conv_b      = (const float*)d_in[5];
    const float* W_xp        = (const float*)d_in[6];
    const float* W_dt        = (const float*)d_in[7];
    const float* b_dt        = (const float*)d_in[8];
    const float* A_log       = (const float*)d_in[9];
    const float* D_param     = (const float*)d_in[10];
    const float* W_out       = (const float*)d_in[11];
    float* out = (float*)d_out;

    const int smem_win  = (D_MODEL + 3 * 4096) * 4;   // 64 KB
    const int smem_wout = (D_INNER + 3 * 4096) * 4;   // 80 KB
    cudaFuncSetAttribute(k_win_p,  cudaFuncAttributeMaxDynamicSharedMemorySize, smem_win);
    cudaFuncSetAttribute(k_wout_p, cudaFuncAttributeMaxDynamicSharedMemorySize, smem_wout);

    k_win_p <<<GRID_P, 256, smem_win>>>(W_in, x, conv_buffer, conv_w, conv_b);
    k_xp    <<<dim3(XP_DIM, D_INNER / KT_XP), 256>>>(W_xp, out);
    k_ssm   <<<D_INNER / 256, 256>>>(W_dt, b_dt, ssm_state, A_log, D_param, out);
    k_wout_p<<<GRID_P, 256, smem_wout>>>(W_out, out);
}

// round 5
// speedup vs baseline: 1.1082x; 1.1082x over previous
#include <cuda_runtime.h>
#include <math.h>

#define D_INNER 8192
#define D_MODEL 4096
#define DT_RANK 8
#define D_STATE 16
#define XP_DIM  (DT_RANK + 2 * D_STATE)   // 40
#define KT_XP   1024

// Scratch
__device__ float g_x_conv[D_INNER];
__device__ float g_z_silu[D_INNER];
__device__ float g_xp[XP_DIM];
__device__ float g_y[D_INNER];

// ---------------------------------------------------------------------------
// Kernel 1: xz = W_in @ x (16384 x 4096) + fused conv/silu epilogue.
// 128-thread blocks, warp-per-row, NO smem / NO barriers. x read via L1
// (persists across CTAs within the launch). grid = 4096.
// ---------------------------------------------------------------------------
__global__ __launch_bounds__(128, 12) void k_win(
    const float* __restrict__ W_in,
    const float* __restrict__ x,
    const float* __restrict__ conv_buffer,
    const float* __restrict__ conv_w,
    const float* __restrict__ conv_b)
{
    const int tid  = threadIdx.x;
    const int lane = tid & 31;
    const int warp = tid >> 5;
    if (blockIdx.x == 0 && tid < XP_DIM) g_xp[tid] = 0.0f;

    const int row = blockIdx.x * 4 + warp;
    const float4* w4 = (const float4*)(W_in + (size_t)row * D_MODEL);
    const float4* x4 = (const float4*)x;

    float acc0 = 0.0f, acc1 = 0.0f;
    #pragma unroll
    for (int i = lane; i < D_MODEL / 4; i += 128) {
        float4 wa = __ldcs(&w4[i]);
        float4 wb = __ldcs(&w4[i + 32]);
        float4 wc = __ldcs(&w4[i + 64]);
        float4 wd = __ldcs(&w4[i + 96]);
        float4 va = __ldg(&x4[i]);
        float4 vb = __ldg(&x4[i + 32]);
        float4 vc = __ldg(&x4[i + 64]);
        float4 vd = __ldg(&x4[i + 96]);
        acc0 = fmaf(wa.x, va.x, acc0); acc0 = fmaf(wa.y, va.y, acc0);
        acc0 = fmaf(wa.z, va.z, acc0); acc0 = fmaf(wa.w, va.w, acc0);
        acc1 = fmaf(wb.x, vb.x, acc1); acc1 = fmaf(wb.y, vb.y, acc1);
        acc1 = fmaf(wb.z, vb.z, acc1); acc1 = fmaf(wb.w, vb.w, acc1);
        acc0 = fmaf(wc.x, vc.x, acc0); acc0 = fmaf(wc.y, vc.y, acc0);
        acc0 = fmaf(wc.z, vc.z, acc0); acc0 = fmaf(wc.w, vc.w, acc0);
        acc1 = fmaf(wd.x, vd.x, acc1); acc1 = fmaf(wd.y, vd.y, acc1);
        acc1 = fmaf(wd.z, vd.z, acc1); acc1 = fmaf(wd.w, vd.w, acc1);
    }
    float acc = acc0 + acc1;
    #pragma unroll
    for (int o = 16; o; o >>= 1) acc += __shfl_xor_sync(0xffffffffu, acc, o);

    if (lane == 0) {
        if (row < D_INNER) {
            float v  = acc;
            float b1 = conv_buffer[row * 3 + 1];
            float b2 = conv_buffer[row * 3 + 2];
            float4 cw = ((const float4*)conv_w)[row];
            float s = fmaf(b1, cw.x, fmaf(b2, cw.y, fmaf(v, cw.z, fmaf(v, cw.w, conv_b[row]))));
            g_x_conv[row] = s / (1.0f + expf(-s));
        } else {
            float v = acc;
            g_z_silu[row - D_INNER] = v / (1.0f + expf(-v));
        }
    }
}

// ---------------------------------------------------------------------------
// Kernel 2: xp = W_xp @ x_conv  (40 x 8192). Split-K grid (40, 8),
// atomicAdd into g_xp. Also zeroes d_out[0:4096] for k_wout's atomics.
// ---------------------------------------------------------------------------
__global__ __launch_bounds__(256) void k_xp(const float* __restrict__ W_xp,
                                            float* __restrict__ d_out)
{
    __shared__ float red[8];
    const int row   = blockIdx.x;
    const int kbase = blockIdx.y * KT_XP;
    const int tid   = threadIdx.x;

    const int bflat = blockIdx.y * XP_DIM + blockIdx.x;
    if (bflat < D_MODEL / 256) d_out[bflat * 256 + tid] = 0.0f;

    const float4* w4 = (const float4*)(W_xp + (size_t)row * D_INNER + kbase);
    const float4* v4 = (const float4*)(g_x_conv + kbase);

    float acc = 0.0f;
    #pragma unroll
    for (int i = tid; i < KT_XP / 4; i += 256) {
        float4 w = __ldcs(&w4[i]);
        float4 v = v4[i];
        acc = fmaf(w.x, v.x, acc);
        acc = fmaf(w.y, v.y, acc);
        acc = fmaf(w.z, v.z, acc);
        acc = fmaf(w.w, v.w, acc);
    }
    #pragma unroll
    for (int o = 16; o; o >>= 1) acc += __shfl_xor_sync(0xffffffffu, acc, o);
    const int warp = tid >> 5, lane = tid & 31;
    if (lane == 0) red[warp] = acc;
    __syncthreads();
    if (warp == 0) {
        float a = (lane < 8) ? red[lane] : 0.0f;
        #pragma unroll
        for (int o = 4; o; o >>= 1) a += __shfl_xor_sync(0xffffffffu, a, o);
        if (lane == 0) atomicAdd(&g_xp[row], a);
    }
}

// ---------------------------------------------------------------------------
// Kernel 3: per-channel SSM update. Writes new_h into d_out[4096:], y -> g_y.
// ---------------------------------------------------------------------------
__global__ __launch_bounds__(256) void k_ssm(
    const float* __restrict__ W_dt,
    const float* __restrict__ b_dt,
    const float* __restrict__ ssm_state,
    const float* __restrict__ A_log,
    const float* __restrict__ D_param,
    float* __restrict__ d_out)
{
    __shared__ float sxp[XP_DIM];
    const int tid = threadIdx.x;
    if (tid < XP_DIM) sxp[tid] = g_xp[tid];
    __syncthreads();

    const int ch = blockIdx.x * 256 + tid;

    float dtr = b_dt[ch];
    const float4* wd4 = (const float4*)(W_dt + (size_t)ch * DT_RANK);
    float4 w0 = wd4[0], w1 = wd4[1];
    dtr = fmaf(w0.x, sxp[0], dtr);
    dtr = fmaf(w0.y, sxp[1], dtr);
    dtr = fmaf(w0.z, sxp[2], dtr);
    dtr = fmaf(w0.w, sxp[3], dtr);
    dtr = fmaf(w1.x, sxp[4], dtr);
    dtr = fmaf(w1.y, sxp[5], dtr);
    dtr = fmaf(w1.z, sxp[6], dtr);
    dtr = fmaf(w1.w, sxp[7], dtr);
    float dt = (dtr > 20.0f) ? dtr : log1pf(expf(dtr));

    const float xc = g_x_conv[ch];
    const float* al = A_log + (size_t)ch * D_STATE;
    const float* st = ssm_state + (size_t)ch * D_STATE;
    float* hout = d_out + D_MODEL + (size_t)ch * D_STATE;

    float acc = 0.0f;
    #pragma unroll
    for (int s = 0; s < D_STATE; s++) {
        float A    = -expf(al[s]);
        float abar = expf(dt * A);
        float h    = fmaf(abar, st[s], dt * sxp[DT_RANK + s] * xc);
        hout[s] = h;
        acc = fmaf(h, sxp[DT_RANK + D_STATE + s], acc);
    }
    g_y[ch] = fmaf(D_param[ch], xc, acc) * g_z_silu[ch];
}

// ---------------------------------------------------------------------------
// Kernel 4: out = W_out @ y (4096 x 8192). 128-thread blocks, warp per
// (row, K-half): each warp streams a contiguous 16KB half-row; y via L1.
// NO smem / NO barriers. grid = 2048. atomicAdd (out zeroed by k_xp).
// ---------------------------------------------------------------------------
__global__ __launch_bounds__(128, 12) void k_wout(
    const float* __restrict__ W_out,
    float* __restrict__ out)
{
    const int tid  = threadIdx.x;
    const int lane = tid & 31;
    const int g    = blockIdx.x * 4 + (tid >> 5);   // global warp id
    const int row  = g >> 1;
    const int kb4  = (g & 1) * (D_MODEL / 4);       // half offset in float4s

    const float4* w4 = (const float4*)(W_out + (size_t)row * D_INNER) + kb4;
    const float4* y4 = (const float4*)g_y + kb4;

    float acc0 = 0.0f, acc1 = 0.0f;
    #pragma unroll
    for (int i = lane; i < D_MODEL / 4; i += 128) {
        float4 wa = __ldcs(&w4[i]);
        float4 wb = __ldcs(&w4[i + 32]);
        float4 wc = __ldcs(&w4[i + 64]);
        float4 wd = __ldcs(&w4[i + 96]);
        float4 va = __ldg(&y4[i]);
        float4 vb = __ldg(&y4[i + 32]);
        float4 vc = __ldg(&y4[i + 64]);
        float4 vd = __ldg(&y4[i + 96]);
        acc0 = fmaf(wa.x, va.x, acc0); acc0 = fmaf(wa.y, va.y, acc0);
        acc0 = fmaf(wa.z, va.z, acc0); acc0 = fmaf(wa.w, va.w, acc0);
        acc1 = fmaf(wb.x, vb.x, acc1); acc1 = fmaf(wb.y, vb.y, acc1);
        acc1 = fmaf(wb.z, vb.z, acc1); acc1 = fmaf(wb.w, vb.w, acc1);
        acc0 = fmaf(wc.x, vc.x, acc0); acc0 = fmaf(wc.y, vc.y, acc0);
        acc0 = fmaf(wc.z, vc.z, acc0); acc0 = fmaf(wc.w, vc.w, acc0);
        acc1 = fmaf(wd.x, vd.x, acc1); acc1 = fmaf(wd.y, vd.y, acc1);
        acc1 = fmaf(wd.z, vd.z, acc1); acc1 = fmaf(wd.w, vd.w, acc1);
    }
    float acc = acc0 + acc1;
    #pragma unroll
    for (int o = 16; o; o >>= 1) acc += __shfl_xor_sync(0xffffffffu, acc, o);
    if (lane == 0) atomicAdd(&out[row], acc);
}

// ---------------------------------------------------------------------------
extern "C" void kernel_launch(void* const* d_in, const int* in_sizes, int n_in,
                              void* d_out, int out_size)
{
    const float* x           = (const float*)d_in[0];
    const float* ssm_state   = (const float*)d_in[1];
    const float* conv_buffer = (const float*)d_in[2];
    const float* W_in        = (const float*)d_in[3];
    const float* conv_w      = (const float*)d_in[4];
    const float* conv_b      = (const float*)d_in[5];
    const float* W_xp        = (const float*)d_in[6];
    const float* W_dt        = (const float*)d_in[7];
    const float* b_dt        = (const float*)d_in[8];
    const float* A_log       = (const float*)d_in[9];
    const float* D_param     = (const float*)d_in[10];
    const float* W_out       = (const float*)d_in[11];
    float* out = (float*)d_out;

    k_win <<<(2 * D_INNER) / 4, 128>>>(W_in, x, conv_buffer, conv_w, conv_b);
    k_xp  <<<dim3(XP_DIM, D_INNER / KT_XP), 256>>>(W_xp, out);
    k_ssm <<<D_INNER / 256, 256>>>(W_dt, b_dt, ssm_state, A_log, D_param, out);
    k_wout<<<2 * D_MODEL / 4, 128>>>(W_out, out);
}

// round 7
// speedup vs baseline: 1.1218x; 1.0122x over previous
#include <cuda_runtime.h>
#include <math.h>

#define D_INNER 8192
#define D_MODEL 4096
#define DT_RANK 8
#define D_STATE 16
#define XP_DIM  (DT_RANK + 2 * D_STATE)   // 40
#define KT_XP   1024

// Scratch
__device__ float g_x_conv[D_INNER];
__device__ float g_z_silu[D_INNER];
__device__ float g_xp[XP_DIM];
__device__ float g_y[D_INNER];

// ---------------------------------------------------------------------------
// Kernel 1: xz = W_in @ x (16384 x 4096) + fused conv/silu epilogue.
// 128-thread blocks, 16 blocks/SM (32-reg budget), warp-per-row, no smem.
// grid = 4096.
// ---------------------------------------------------------------------------
__global__ __launch_bounds__(128, 16) void k_win(
    const float* __restrict__ W_in,
    const float* __restrict__ x,
    const float* __restrict__ conv_buffer,
    const float* __restrict__ conv_w,
    const float* __restrict__ conv_b)
{
    const int tid  = threadIdx.x;
    const int lane = tid & 31;
    const int warp = tid >> 5;
    if (blockIdx.x == 0 && tid < XP_DIM) g_xp[tid] = 0.0f;

    const int row = blockIdx.x * 4 + warp;
    const float4* w4 = (const float4*)(W_in + (size_t)row * D_MODEL);
    const float4* x4 = (const float4*)x;

    float acc0 = 0.0f, acc1 = 0.0f;
    #pragma unroll
    for (int i = lane; i < D_MODEL / 4; i += 64) {
        float4 wa = __ldcs(&w4[i]);
        float4 wb = __ldcs(&w4[i + 32]);
        float4 va = x4[i];
        float4 vb = x4[i + 32];
        acc0 = fmaf(wa.x, va.x, acc0); acc0 = fmaf(wa.y, va.y, acc0);
        acc0 = fmaf(wa.z, va.z, acc0); acc0 = fmaf(wa.w, va.w, acc0);
        acc1 = fmaf(wb.x, vb.x, acc1); acc1 = fmaf(wb.y, vb.y, acc1);
        acc1 = fmaf(wb.z, vb.z, acc1); acc1 = fmaf(wb.w, vb.w, acc1);
    }
    float acc = acc0 + acc1;
    #pragma unroll
    for (int o = 16; o; o >>= 1) acc += __shfl_xor_sync(0xffffffffu, acc, o);

    if (lane == 0) {
        if (row < D_INNER) {
            float v  = acc;
            float b1 = conv_buffer[row * 3 + 1];
            float b2 = conv_buffer[row * 3 + 2];
            float4 cw = ((const float4*)conv_w)[row];
            float s = fmaf(b1, cw.x, fmaf(b2, cw.y, fmaf(v, cw.z, fmaf(v, cw.w, conv_b[row]))));
            g_x_conv[row] = s / (1.0f + expf(-s));
        } else {
            float v = acc;
            g_z_silu[row - D_INNER] = v / (1.0f + expf(-v));
        }
    }
}

// ---------------------------------------------------------------------------
// Kernel 2: xp = W_xp @ x_conv  (40 x 8192). Split-K grid (40, 8),
// atomicAdd into g_xp. Also zeroes d_out[0:4096] for k_wout's atomics.
// ---------------------------------------------------------------------------
__global__ __launch_bounds__(256) void k_xp(const float* __restrict__ W_xp,
                                            float* __restrict__ d_out)
{
    __shared__ float red[8];
    const int row   = blockIdx.x;
    const int kbase = blockIdx.y * KT_XP;
    const int tid   = threadIdx.x;

    const int bflat = blockIdx.y * XP_DIM + blockIdx.x;
    if (bflat < D_MODEL / 256) d_out[bflat * 256 + tid] = 0.0f;

    const float4* w4 = (const float4*)(W_xp + (size_t)row * D_INNER + kbase);
    const float4* v4 = (const float4*)(g_x_conv + kbase);

    float acc = 0.0f;
    #pragma unroll
    for (int i = tid; i < KT_XP / 4; i += 256) {
        float4 w = __ldcs(&w4[i]);
        float4 v = v4[i];
        acc = fmaf(w.x, v.x, acc);
        acc = fmaf(w.y, v.y, acc);
        acc = fmaf(w.z, v.z, acc);
        acc = fmaf(w.w, v.w, acc);
    }
    #pragma unroll
    for (int o = 16; o; o >>= 1) acc += __shfl_xor_sync(0xffffffffu, acc, o);
    const int warp = tid >> 5, lane = tid & 31;
    if (lane == 0) red[warp] = acc;
    __syncthreads();
    if (warp == 0) {
        float a = (lane < 8) ? red[lane] : 0.0f;
        #pragma unroll
        for (int o = 4; o; o >>= 1) a += __shfl_xor_sync(0xffffffffu, a, o);
        if (lane == 0) atomicAdd(&g_xp[row], a);
    }
}

// ---------------------------------------------------------------------------
// Kernel 3: per-channel SSM update. Writes new_h into d_out[4096:], y -> g_y.
// ---------------------------------------------------------------------------
__global__ __launch_bounds__(256) void k_ssm(
    const float* __restrict__ W_dt,
    const float* __restrict__ b_dt,
    const float* __restrict__ ssm_state,
    const float* __restrict__ A_log,
    const float* __restrict__ D_param,
    float* __restrict__ d_out)
{
    __shared__ float sxp[XP_DIM];
    const int tid = threadIdx.x;
    if (tid < XP_DIM) sxp[tid] = g_xp[tid];
    __syncthreads();

    const int ch = blockIdx.x * 256 + tid;

    float dtr = b_dt[ch];
    const float4* wd4 = (const float4*)(W_dt + (size_t)ch * DT_RANK);
    float4 w0 = wd4[0], w1 = wd4[1];
    dtr = fmaf(w0.x, sxp[0], dtr);
    dtr = fmaf(w0.y, sxp[1], dtr);
    dtr = fmaf(w0.z, sxp[2], dtr);
    dtr = fmaf(w0.w, sxp[3], dtr);
    dtr = fmaf(w1.x, sxp[4], dtr);
    dtr = fmaf(w1.y, sxp[5], dtr);
    dtr = fmaf(w1.z, sxp[6], dtr);
    dtr = fmaf(w1.w, sxp[7], dtr);
    float dt = (dtr > 20.0f) ? dtr : log1pf(expf(dtr));

    const float xc = g_x_conv[ch];
    const float* al = A_log + (size_t)ch * D_STATE;
    const float* st = ssm_state + (size_t)ch * D_STATE;
    float* hout = d_out + D_MODEL + (size_t)ch * D_STATE;

    float acc = 0.0f;
    #pragma unroll
    for (int s = 0; s < D_STATE; s++) {
        float A    = -expf(al[s]);
        float abar = expf(dt * A);
        float h    = fmaf(abar, st[s], dt * sxp[DT_RANK + s] * xc);
        hout[s] = h;
        acc = fmaf(h, sxp[DT_RANK + D_STATE + s], acc);
    }
    g_y[ch] = fmaf(D_param[ch], xc, acc) * g_z_silu[ch];
}

// ---------------------------------------------------------------------------
// Kernel 4: out = W_out @ y (4096 x 8192). 128-thread blocks, 16 blocks/SM,
// warp per (row, K-half): contiguous 16KB half-row stream. grid = 2048
// (single resident wave). atomicAdd (out zeroed by k_xp).
// ---------------------------------------------------------------------------
__global__ __launch_bounds__(128, 16) void k_wout(
    const float* __restrict__ W_out,
    float* __restrict__ out)
{
    const int tid  = threadIdx.x;
    const int lane = tid & 31;
    const int g    = blockIdx.x * 4 + (tid >> 5);   // global warp id
    const int row  = g >> 1;
    const int kb4  = (g & 1) * (D_MODEL / 4);       // half offset in float4s

    const float4* w4 = (const float4*)(W_out + (size_t)row * D_INNER) + kb4;
    const float4* y4 = (const float4*)g_y + kb4;

    float acc0 = 0.0f, acc1 = 0.0f;
    #pragma unroll
    for (int i = lane; i < D_MODEL / 4; i += 64) {
        float4 wa = __ldcs(&w4[i]);
        float4 wb = __ldcs(&w4[i + 32]);
        float4 va = y4[i];
        float4 vb = y4[i + 32];
        acc0 = fmaf(wa.x, va.x, acc0); acc0 = fmaf(wa.y, va.y, acc0);
        acc0 = fmaf(wa.z, va.z, acc0); acc0 = fmaf(wa.w, va.w, acc0);
        acc1 = fmaf(wb.x, vb.x, acc1); acc1 = fmaf(wb.y, vb.y, acc1);
        acc1 = fmaf(wb.z, vb.z, acc1); acc1 = fmaf(wb.w, vb.w, acc1);
    }
    float acc = acc0 + acc1;
    #pragma unroll
    for (int o = 16; o; o >>= 1) acc += __shfl_xor_sync(0xffffffffu, acc, o);
    if (lane == 0) atomicAdd(&out[row], acc);
}

// ---------------------------------------------------------------------------
extern "C" void kernel_launch(void* const* d_in, const int* in_sizes, int n_in,
                              void* d_out, int out_size)
{
    const float* x           = (const float*)d_in[0];
    const float* ssm_state   = (const float*)d_in[1];
    const float* conv_buffer = (const float*)d_in[2];
    const float* W_in        = (const float*)d_in[3];
    const float* conv_w      = (const float*)d_in[4];
    const float* conv_b      = (const float*)d_in[5];
    const float* W_xp        = (const float*)d_in[6];
    const float* W_dt        = (const float*)d_in[7];
    const float* b_dt        = (const float*)d_in[8];
    const float* A_log       = (const float*)d_in[9];
    const float* D_param     = (const float*)d_in[10];
    const float* W_out       = (const float*)d_in[11];
    float* out = (float*)d_out;

    k_win <<<(2 * D_INNER) / 4, 128>>>(W_in, x, conv_buffer, conv_w, conv_b);
    k_xp  <<<dim3(XP_DIM, D_INNER / KT_XP), 256>>>(W_xp, out);
    k_ssm <<<D_INNER / 256, 256>>>(W_dt, b_dt, ssm_state, A_log, D_param, out);
    k_wout<<<2 * D_MODEL / 4, 128>>>(W_out, out);
}